// round 3
// baseline (speedup 1.0000x reference)
#include <cuda_runtime.h>
#include <cuda_bf16.h>
#include <mma.h>
using namespace nvcuda;

#define DM 16384
#define DS 512
#define DH 256
#define DG 768
#define DKE 320
#define DE 300
#define DC2 512

__device__ __align__(256) __nv_bfloat16 g_ehi[(size_t)DM*DKE], g_elo[(size_t)DM*DKE];
__device__ __align__(256) __nv_bfloat16 g_wihh[2ull*DG*DKE], g_wihl[2ull*DG*DKE];
__device__ __align__(256) __nv_bfloat16 g_whhh[2ull*DG*DH], g_whhl[2ull*DG*DH];
__device__ __align__(256) __nv_bfloat16 g_mwh[(size_t)DC2*DC2], g_mwl[(size_t)DC2*DC2];
__device__ __align__(256) float g_proj[2ull*DM*DG];
__device__ __align__(256) float g_ppad[2*DG];
__device__ __align__(256) float g_hg[2ull*DM*DG];
__device__ __align__(256) float g_h[2ull*DM*DH];
__device__ __align__(256) __nv_bfloat16 g_hhi[2ull*DM*DH], g_hlo[2ull*DM*DH];
__device__ __align__(256) float g_hidden[(size_t)DM*DC2];
__device__ __align__(256) __nv_bfloat16 g_nhi[(size_t)DM*DC2], g_nlo[(size_t)DM*DC2];
__device__ __align__(256) float g_mlp[(size_t)DM*DC2];
__device__ __align__(256) float g_bns[128*DC2], g_bnq[128*DC2];
__device__ __align__(256) float g_scale[DC2], g_shift[DC2];
__device__ __align__(256) float g_pool[32*DC2];

__device__ __forceinline__ void cp16(void* s, const void* g) {
    unsigned a = (unsigned)__cvta_generic_to_shared(s);
    asm volatile("cp.async.cg.shared.global [%0], [%1], 16;\n" :: "r"(a), "l"(g));
}
__device__ __forceinline__ void spl(float v, __nv_bfloat16* hi, __nv_bfloat16* lo) {
    __nv_bfloat16 h = __float2bfloat16(v);
    *hi = h; *lo = __float2bfloat16(v - __bfloat162float(h));
}

// ---------- prep ----------
__global__ void prep_w(const float* wf, const float* hf, const float* wb, const float* hb) {
    int b = blockIdx.x; int dir = b / DG, g = b % DG; int k = threadIdx.x;
    const float* wi = dir ? wb : wf; const float* wh = dir ? hb : hf;
    float v = (k < DE) ? wi[(size_t)g*DE + k] : 0.f;
    size_t o = ((size_t)dir*DG + g)*DKE + k;
    spl(v, &g_wihh[o], &g_wihl[o]);
    if (k < DH) {
        size_t o2 = ((size_t)dir*DG + g)*DH + k;
        spl(wh[(size_t)g*DH + k], &g_whhh[o2], &g_whhl[o2]);
    }
}
__global__ void prep_mlp(const float* mw) {
    size_t i = (size_t)blockIdx.x*DC2 + threadIdx.x;
    spl(mw[i], &g_mwh[i], &g_mwl[i]);
}
__global__ void pad_projk(const float* wf, const float* wb, const float* emb) {
    int idx = blockIdx.x*256 + threadIdx.x;
    int dir = idx / DG, g = idx % DG;
    const float* wi = dir ? wb : wf;
    float a = 0.f;
    for (int e = 0; e < DE; ++e) a += wi[(size_t)g*DE + e] * emb[e];
    g_ppad[idx] = a;
}
__global__ void gather_emb(const int* x, const float* emb) {
    int m = blockIdx.x, k = threadIdx.x;
    int tok = x[m];
    float v = (k < DE) ? emb[(size_t)tok*DE + k] : 0.f;
    spl(v, &g_ehi[(size_t)m*DKE + k], &g_elo[(size_t)m*DKE + k]);
}

// ---------- generic 3-split GEMM: C = A @ B^T, tile 128x128, 256 thr ----------
__global__ void __launch_bounds__(256) gemm3(int mode) {
    extern __shared__ __nv_bfloat16 sm[];
    const int SA = 128*40;
    const __nv_bfloat16 *Ah, *Al, *Bh, *Bl; float* C; int K, N;
    int z = blockIdx.z;
    if (mode == 0) { Ah = g_ehi; Al = g_elo;
        Bh = g_wihh + (size_t)z*DG*DKE; Bl = g_wihl + (size_t)z*DG*DKE;
        C = g_proj + (size_t)z*DM*DG; K = DKE; N = DG; }
    else if (mode == 1) { Ah = g_hhi + (size_t)z*DM*DH; Al = g_hlo + (size_t)z*DM*DH;
        Bh = g_whhh + (size_t)z*DG*DH; Bl = g_whhl + (size_t)z*DG*DH;
        C = g_hg + (size_t)z*DM*DG; K = DH; N = DG; }
    else { Ah = g_nhi; Al = g_nlo; Bh = g_mwh; Bl = g_mwl; C = g_mlp; K = DC2; N = DC2; }
    int m0 = blockIdx.x*128, n0 = blockIdx.y*128, t = threadIdx.x;
    int NK = K >> 5;
    wmma::fragment<wmma::accumulator,16,16,16,float> acc[4][2];
    #pragma unroll
    for (int i = 0; i < 4; ++i)
        #pragma unroll
        for (int j = 0; j < 2; ++j) wmma::fill_fragment(acc[i][j], 0.f);

    auto load = [&](int kc, int st) {
        __nv_bfloat16* b = sm + (size_t)st*4*SA;
        int k0 = kc*32;
        #pragma unroll
        for (int c = t; c < 512; c += 256) {
            int r = c >> 2, c8 = (c & 3)*8;
            cp16(b +        r*40 + c8, Ah + (size_t)(m0+r)*K + k0 + c8);
            cp16(b +   SA + r*40 + c8, Al + (size_t)(m0+r)*K + k0 + c8);
            cp16(b + 2*SA + r*40 + c8, Bh + (size_t)(n0+r)*K + k0 + c8);
            cp16(b + 3*SA + r*40 + c8, Bl + (size_t)(n0+r)*K + k0 + c8);
        }
        asm volatile("cp.async.commit_group;\n");
    };
    int w = t >> 5, wm = w & 1, wn = w >> 1;   // 2 x 4 warp grid
    load(0, 0);
    for (int kc = 0; kc < NK; ++kc) {
        int st = kc & 1;
        if (kc + 1 < NK) { load(kc+1, st^1); asm volatile("cp.async.wait_group 1;\n"); }
        else             { asm volatile("cp.async.wait_group 0;\n"); }
        __syncthreads();
        const __nv_bfloat16 *pA = sm + (size_t)st*4*SA, *pAl = pA + SA,
                            *pB = pA + 2*SA, *pBl = pA + 3*SA;
        #pragma unroll
        for (int kk = 0; kk < 32; kk += 16) {
            wmma::fragment<wmma::matrix_a,16,16,16,__nv_bfloat16,wmma::row_major> fa[4], fal[4];
            wmma::fragment<wmma::matrix_b,16,16,16,__nv_bfloat16,wmma::col_major> fb[2], fbl[2];
            #pragma unroll
            for (int i = 0; i < 4; ++i) {
                wmma::load_matrix_sync(fa[i],  pA  + (wm*64 + i*16)*40 + kk, 40);
                wmma::load_matrix_sync(fal[i], pAl + (wm*64 + i*16)*40 + kk, 40);
            }
            #pragma unroll
            for (int j = 0; j < 2; ++j) {
                wmma::load_matrix_sync(fb[j],  pB  + (wn*32 + j*16)*40 + kk, 40);
                wmma::load_matrix_sync(fbl[j], pBl + (wn*32 + j*16)*40 + kk, 40);
            }
            #pragma unroll
            for (int i = 0; i < 4; ++i)
                #pragma unroll
                for (int j = 0; j < 2; ++j) {
                    wmma::mma_sync(acc[i][j], fa[i],  fb[j],  acc[i][j]);
                    wmma::mma_sync(acc[i][j], fal[i], fb[j],  acc[i][j]);
                    wmma::mma_sync(acc[i][j], fa[i],  fbl[j], acc[i][j]);
                }
        }
        __syncthreads();
    }
    #pragma unroll
    for (int i = 0; i < 4; ++i)
        #pragma unroll
        for (int j = 0; j < 2; ++j)
            wmma::store_matrix_sync(C + (size_t)(m0 + wm*64 + i*16)*N + n0 + wn*32 + j*16,
                                    acc[i][j], N, wmma::mem_row_major);
}

// ---------- fused gate nonlinearity / state update ----------
__global__ void gru_update(const float* bihf, const float* bhhf,
                           const float* bihb, const float* bhhb,
                           int offF, int offB, int use_hg) {
    int m = blockIdx.x, dir = blockIdx.y, hh = threadIdx.x;
    int off = dir ? offB : offF;
    int s = m & (DS - 1);
    int j = s + off;
    const float* bih = dir ? bihb : bihf;
    const float* bhh = dir ? bhhb : bhhf;
    const float* pr = (j >= 0 && j < DS) ? g_proj + ((size_t)dir*DM + m + off)*DG
                                         : g_ppad + dir*DG;
    float xr = pr[hh] + bih[hh];
    float xz = pr[DH + hh] + bih[DH + hh];
    float xn = pr[2*DH + hh] + bih[2*DH + hh];
    float hr = bhh[hh], hz = bhh[DH + hh], hn = bhh[2*DH + hh], hold = 0.f;
    size_t hidx = ((size_t)dir*DM + m)*DH + hh;
    if (use_hg) {
        const float* hg = g_hg + ((size_t)dir*DM + m)*DG;
        hr += hg[hh]; hz += hg[DH + hh]; hn += hg[2*DH + hh];
        hold = g_h[hidx];
    }
    float r  = 1.f / (1.f + __expf(-(xr + hr)));
    float zz = 1.f / (1.f + __expf(-(xz + hz)));
    float n  = tanhf(xn + r*hn);
    float hv = (1.f - zz)*n + zz*hold;
    g_h[hidx] = hv;
    spl(hv, &g_hhi[hidx], &g_hlo[hidx]);
}

// ---------- tail ----------
__global__ void concat_stats(const int* x) {
    int blk = blockIdx.x, c = threadIdx.x;
    float s1 = 0, q1 = 0, s2 = 0, q2 = 0;
    for (int r = 0; r < 128; ++r) {
        int m = blk*128 + r;
        float mk = (x[m] > 0) ? 1.f : 0.f;
        float a = g_h[(size_t)m*DH + c] * mk;
        float b = g_h[((size_t)DM + m)*DH + c] * mk;
        g_hidden[(size_t)m*DC2 + c] = a;
        g_hidden[(size_t)m*DC2 + DH + c] = b;
        s1 += a; q1 += a*a; s2 += b; q2 += b*b;
    }
    g_bns[blk*DC2 + c] = s1;      g_bnq[blk*DC2 + c] = q1;
    g_bns[blk*DC2 + DH + c] = s2; g_bnq[blk*DC2 + DH + c] = q2;
}
__global__ void bn_fin(const float* gam, const float* bet) {
    int c = threadIdx.x;
    float s = 0, q = 0;
    for (int b = 0; b < 128; ++b) { s += g_bns[b*DC2 + c]; q += g_bnq[b*DC2 + c]; }
    float mu = s / (float)DM;
    float var = q / (float)DM - mu*mu;
    float sc = gam[c] * rsqrtf(var + 1e-5f);
    g_scale[c] = sc; g_shift[c] = bet[c] - mu*sc;
}
__global__ void norm_split(const int* x) {
    int m = blockIdx.x, c = threadIdx.x;
    float mk = (x[m] > 0) ? 1.f : 0.f;
    float v = (g_hidden[(size_t)m*DC2 + c] * g_scale[c] + g_shift[c]) * mk;
    spl(v, &g_nhi[(size_t)m*DC2 + c], &g_nlo[(size_t)m*DC2 + c]);
}
__global__ void poolk(const int* x, const float* mb) {
    int b = blockIdx.x, c = threadIdx.x;
    float bias = mb[c], mx = -3.4e38f;
    for (int s = 0; s < DS; ++s) {
        int m = b*DS + s;
        float v = (x[m] > 0) ? g_mlp[(size_t)m*DC2 + c] + bias : -65500.f;
        mx = fmaxf(mx, v);
    }
    g_pool[b*DC2 + c] = mx;
}
__global__ void headk(const float* lw, const float* lb, float* out) {
    int b = blockIdx.x, w = threadIdx.x >> 5, l = threadIdx.x & 31;
    float s = 0;
    for (int i = l; i < DC2; i += 32) s += g_pool[b*DC2 + i] * lw[(size_t)w*DC2 + i];
    #pragma unroll
    for (int o = 16; o; o >>= 1) s += __shfl_xor_sync(~0u, s, o);
    if (!l) out[b*2 + w] = s + lb[w];
}

extern "C" void kernel_launch(void* const* d_in, const int* in_sizes, int n_in,
                              void* d_out, int out_size) {
    const int*   x    = (const int*)d_in[0];
    const float* emb  = (const float*)d_in[5];
    const float* wihf = (const float*)d_in[6];
    const float* whhf = (const float*)d_in[7];
    const float* bihf = (const float*)d_in[8];
    const float* bhhf = (const float*)d_in[9];
    const float* wihb = (const float*)d_in[10];
    const float* whhb = (const float*)d_in[11];
    const float* bihb = (const float*)d_in[12];
    const float* bhhb = (const float*)d_in[13];
    const float* gam  = (const float*)d_in[14];
    const float* bet  = (const float*)d_in[15];
    const float* mw   = (const float*)d_in[16];
    const float* mb   = (const float*)d_in[17];
    const float* lw   = (const float*)d_in[18];
    const float* lb   = (const float*)d_in[19];
    float* out = (float*)d_out;

    cudaFuncSetAttribute(gemm3, cudaFuncAttributeMaxDynamicSharedMemorySize, 81920);

    prep_w<<<2*DG, DKE>>>(wihf, whhf, wihb, whhb);
    prep_mlp<<<DC2, DC2>>>(mw);
    pad_projk<<<(2*DG)/256, 256>>>(wihf, wihb, emb);
    gather_emb<<<DM, DKE>>>(x, emb);

    dim3 gp(DM/128, DG/128, 2);
    gemm3<<<gp, 256, 81920>>>(0);                       // proj (both dirs)
    gru_update<<<dim3(DM,2), DH>>>(bihf, bhhf, bihb, bhhb, -14, 14, 0);
    for (int i = 1; i < 15; ++i) {
        gemm3<<<gp, 256, 81920>>>(1);                   // h @ Whh^T
        gru_update<<<dim3(DM,2), DH>>>(bihf, bhhf, bihb, bhhb, i - 14, 14 - i, 1);
    }
    concat_stats<<<128, 256>>>(x);
    bn_fin<<<1, DC2>>>(gam, bet);
    norm_split<<<DM, DC2>>>(x);
    gemm3<<<dim3(DM/128, DC2/128, 1), 256, 81920>>>(2); // MLP
    poolk<<<32, DC2>>>(x, mb);
    headk<<<32, 64>>>(lw, lb, out);
}